// round 15
// baseline (speedup 1.0000x reference)
#include <cuda_runtime.h>
#include <cuda_bf16.h>
#include <cstdint>
#include <cstddef>

#define EPS 1e-5f

// ---------------- problem constants ----------------
#define B   4096
#define TT  60
#define TS  30
#define H   512
#define LAT 128
#define OUT 14
#define NH  4
#define DH  128
#define NG  2560
#define K2H 1024

// ---------------- device scratch ----------------
__device__ float d_combined[(size_t)B * TS * H];
__device__ float d_G0      [(size_t)B * NG];
__device__ float d_G1      [(size_t)B * NG];
__device__ float d_c       [(size_t)2 * B * H];
__device__ float d_kv      [(size_t)B * TS * K2H];
__device__ float d_q       [(size_t)B * H];
__device__ float d_lat     [(size_t)B * LAT];

#define HW  256
__device__ uint32_t d_combH[(size_t)B * TS * HW];
__device__ uint32_t d_combL[(size_t)B * TS * HW];
__device__ uint32_t d_seqH [(size_t)B * TS * HW];
__device__ uint32_t d_seqL [(size_t)B * TS * HW];
__device__ uint32_t d_hH   [(size_t)3 * B * HW];   // h0a | h0b | h1
__device__ uint32_t d_hL   [(size_t)3 * B * HW];
__device__ uint32_t d_attH [(size_t)B * HW];
__device__ uint32_t d_attL [(size_t)B * HW];
__device__ uint32_t d_finH [(size_t)B * HW];
__device__ uint32_t d_finL [(size_t)B * HW];

#define OFF_W0   0
#define OFF_W1   1310720
#define OFF_AIN  2621440
#define OFF_AOUT 3014656
#define OFF_BNK  3145728
#define W_WORDS  3178496
__device__ uint32_t d_Wh[(size_t)W_WORDS];
__device__ uint32_t d_Wl[(size_t)W_WORDS];

// ---------------- helpers ----------------
__device__ __forceinline__ uint32_t pack_bf(float a, float b) {
    __nv_bfloat162 t = __floats2bfloat162_rn(a, b);
    return *reinterpret_cast<uint32_t*>(&t);
}
__device__ __forceinline__ float bf_hi(float x) {
    return __bfloat162float(__float2bfloat16_rn(x));
}
__device__ __forceinline__ uint32_t smem_u32(const void* p) {
    uint32_t a;
    asm("{ .reg .u64 t; cvta.to.shared.u64 t, %1; cvt.u32.u64 %0, t; }" : "=r"(a) : "l"(p));
    return a;
}

#define MMA16(d, a, b) \
    asm volatile( \
        "mma.sync.aligned.m16n8k16.row.col.f32.bf16.bf16.f32 " \
        "{%0,%1,%2,%3}, {%4,%5,%6,%7}, {%8,%9}, {%0,%1,%2,%3};" \
        : "+f"((d)[0]), "+f"((d)[1]), "+f"((d)[2]), "+f"((d)[3]) \
        : "r"((a)[0]), "r"((a)[1]), "r"((a)[2]), "r"((a)[3]), \
          "r"((b)[0]), "r"((b)[1]))

#define LDSM4(v, addr) \
    asm volatile("ldmatrix.sync.aligned.m8n8.x4.shared.b16 {%0,%1,%2,%3}, [%4];" \
        : "=r"((v)[0]), "=r"((v)[1]), "=r"((v)[2]), "=r"((v)[3]) : "r"(addr))

#define CP16(dst, src) \
    asm volatile("cp.async.cg.shared.global [%0], [%1], 16;" :: "r"(dst), "l"(src))
#define CPCOMMIT() asm volatile("cp.async.commit_group;" ::: "memory")
#define CPWAIT1()  asm volatile("cp.async.wait_group 1;" ::: "memory")

#define STG_WORDS 8192
#define GEMM_SMEM_BYTES (3 * STG_WORDS * 4)

// ---------------- fused zero init ----------------
__global__ void zero3_kernel(float* __restrict__ p0, int n0,
                             float* __restrict__ p1, int n1,
                             float* __restrict__ p2, int n2) {
    int i = blockIdx.x * blockDim.x + threadIdx.x;
    int stride = gridDim.x * blockDim.x;
    for (int j = i; j < n0; j += stride) p0[j] = 0.0f;
    for (int j = i; j < n1; j += stride) p1[j] = 0.0f;
    for (int j = i; j < n2; j += stride) p2[j] = 0.0f;
}

// ---------------- bf16 hi/lo packed split ----------------
__device__ __forceinline__ void split_range(const float* __restrict__ src,
                                            uint32_t* __restrict__ hi,
                                            uint32_t* __restrict__ lo,
                                            int nwords, int i, int stride) {
    for (; i < nwords; i += stride) {
        float2 v = *(const float2*)(src + 2 * (size_t)i);
        float h0 = bf_hi(v.x), h1 = bf_hi(v.y);
        hi[i] = pack_bf(h0, h1);
        lo[i] = pack_bf(v.x - h0, v.y - h1);
    }
}
__global__ void split5_kernel(
    const float* __restrict__ s0, uint32_t* __restrict__ h0, uint32_t* __restrict__ l0, int n0,
    const float* __restrict__ s1, uint32_t* __restrict__ h1, uint32_t* __restrict__ l1, int n1,
    const float* __restrict__ s2, uint32_t* __restrict__ h2, uint32_t* __restrict__ l2, int n2,
    const float* __restrict__ s3, uint32_t* __restrict__ h3, uint32_t* __restrict__ l3, int n3,
    const float* __restrict__ s4, uint32_t* __restrict__ h4, uint32_t* __restrict__ l4, int n4) {
    int i = blockIdx.x * blockDim.x + threadIdx.x;
    int stride = gridDim.x * blockDim.x;
    split_range(s0, h0, l0, n0, i, stride);
    split_range(s1, h1, l1, n1, i, stride);
    split_range(s2, h2, l2, n2, i, stride);
    split_range(s3, h3, l3, n3, i, stride);
    split_range(s4, h4, l4, n4, i, stride);
}

// ================= bf16x3 GEMM core (128x128 tile, 2 CTA/SM; two A sources) ========
__device__ __forceinline__ void gemm_core(
    const uint32_t* __restrict__ A1h, const uint32_t* __restrict__ A1l,
    int lda1, int K1w,
    const uint32_t* __restrict__ A2h, const uint32_t* __restrict__ A2l,
    int lda2,
    const uint32_t* __restrict__ Wh, const uint32_t* __restrict__ Wl, int Kw,
    const float* __restrict__ bias,
    float* __restrict__ C, int ldc,
    uint32_t* __restrict__ Ch, uint32_t* __restrict__ Cl,
    int N, int m0, int n0, uint32_t smb)
{
    const int tid = threadIdx.x;
    const int wid = tid >> 5, lane = tid & 31;
    const int g = lane >> 2, t4 = lane & 3;
    const int warp_m = wid >> 2, warp_n = wid & 3;

    const int r = tid >> 1, half = tid & 1;
    const int wb = half * 8;
    const int swz = ((r >> 1) & 3) << 2;
    const int so0 = r * 16 + ((wb) ^ swz);
    const int so1 = r * 16 + ((wb + 4) ^ swz);

    const int a_r = lane & 15;
    const int a_k = (lane >> 4) << 2;
    int aoff[4], aswz[4];
    #pragma unroll
    for (int tm = 0; tm < 4; tm++) {
        const int row = warp_m * 64 + tm * 16 + a_r;
        aoff[tm] = row * 16;
        aswz[tm] = ((row >> 1) & 3) << 2;
    }
    const int b_r = (lane & 7) + ((lane >> 4) << 3);
    const int b_k = ((lane >> 3) & 1) << 2;
    int boff[2], bswz[2];
    #pragma unroll
    for (int tp = 0; tp < 2; tp++) {
        const int row = warp_n * 32 + tp * 16 + b_r;
        boff[tp] = row * 16;
        bswz[tp] = ((row >> 1) & 3) << 2;
    }

    float acc[4][4][4];
    #pragma unroll
    for (int i = 0; i < 4; i++)
        #pragma unroll
        for (int j = 0; j < 4; j++)
            #pragma unroll
            for (int e = 0; e < 4; e++) acc[i][j][e] = 0.0f;

    const int NKB = Kw / 16;

    auto issue = [&](int kb, int stage) {
        const int kbw = kb * 16 + wb;
        const uint32_t *ah, *al;
        if (kbw < K1w) {
            ah = A1h + (size_t)(m0 + r) * lda1 + kbw;
            al = A1l + (size_t)(m0 + r) * lda1 + kbw;
        } else {
            ah = A2h + (size_t)(m0 + r) * lda2 + (kbw - K1w);
            al = A2l + (size_t)(m0 + r) * lda2 + (kbw - K1w);
        }
        const uint32_t* bh = Wh + (size_t)(n0 + r) * Kw + kbw;
        const uint32_t* bl = Wl + (size_t)(n0 + r) * Kw + kbw;
        const uint32_t sb = smb + (uint32_t)(stage * STG_WORDS) * 4;
        CP16(sb + so0 * 4, ah);                 CP16(sb + so1 * 4, ah + 4);
        CP16(sb + (2048 + so0) * 4, al);        CP16(sb + (2048 + so1) * 4, al + 4);
        CP16(sb + (4096 + so0) * 4, bh);        CP16(sb + (4096 + so1) * 4, bh + 4);
        CP16(sb + (6144 + so0) * 4, bl);        CP16(sb + (6144 + so1) * 4, bl + 4);
    };

    issue(0, 0); CPCOMMIT();
    issue(1, 1); CPCOMMIT();

    for (int kb = 0; kb < NKB; kb++) {
        CPWAIT1();
        __syncthreads();
        const uint32_t sbase = smb + (uint32_t)((kb % 3) * STG_WORDS) * 4;

        #pragma unroll
        for (int kc = 0; kc < 2; kc++) {
            const int akw = kc * 8 + a_k;
            const int bkw = kc * 8 + b_k;
            uint32_t Bh[2][4], Bl[2][4];
            #pragma unroll
            for (int tp = 0; tp < 2; tp++) {
                const uint32_t bd = sbase + (uint32_t)(4096 + boff[tp] + (bkw ^ bswz[tp])) * 4;
                LDSM4(Bh[tp], bd);
                LDSM4(Bl[tp], bd + 2048 * 4);
            }
            #pragma unroll
            for (int tm = 0; tm < 4; tm++) {
                uint32_t Ahf[4], Alf[4];
                const uint32_t ad = sbase + (uint32_t)(aoff[tm] + (akw ^ aswz[tm])) * 4;
                LDSM4(Ahf, ad);
                LDSM4(Alf, ad + 2048 * 4);
                #pragma unroll
                for (int tn = 0; tn < 4; tn++) {
                    uint32_t* bh = &Bh[tn >> 1][(tn & 1) * 2];
                    uint32_t* bl = &Bl[tn >> 1][(tn & 1) * 2];
                    MMA16(acc[tm][tn], Ahf, bh);
                    MMA16(acc[tm][tn], Ahf, bl);
                    MMA16(acc[tm][tn], Alf, bh);
                }
            }
        }
        if (kb + 2 < NKB) issue(kb + 2, (kb + 2) % 3);
        CPCOMMIT();
    }

    const int Nw = N >> 1;
    #pragma unroll
    for (int tm = 0; tm < 4; tm++) {
        const int row0 = m0 + warp_m * 64 + tm * 16 + g;
        #pragma unroll
        for (int tn = 0; tn < 4; tn++) {
            const int col = n0 + warp_n * 32 + tn * 8 + t4 * 2;
            const float b0 = bias[col], b1 = bias[col + 1];
            const float v00 = acc[tm][tn][0] + b0, v01 = acc[tm][tn][1] + b1;
            const float v10 = acc[tm][tn][2] + b0, v11 = acc[tm][tn][3] + b1;
            if (C) {
                // streaming stores: G / kv outputs are read exactly once
                __stcs((float2*)(C + (size_t)row0 * ldc + col), make_float2(v00, v01));
                __stcs((float2*)(C + (size_t)(row0 + 8) * ldc + col), make_float2(v10, v11));
            }
            if (Ch) {
                const int w = (col >> 1);
                float h00 = bf_hi(v00), h01 = bf_hi(v01);
                float h10 = bf_hi(v10), h11 = bf_hi(v11);
                Ch[(size_t)row0 * Nw + w]       = pack_bf(h00, h01);
                Cl[(size_t)row0 * Nw + w]       = pack_bf(v00 - h00, v01 - h01);
                Ch[(size_t)(row0 + 8) * Nw + w] = pack_bf(h10, h11);
                Cl[(size_t)(row0 + 8) * Nw + w] = pack_bf(v10 - h10, v11 - h11);
            }
        }
    }
}

__global__ __launch_bounds__(256, 2) void gemm_bf16(
    const uint32_t* __restrict__ A1h, const uint32_t* __restrict__ A1l,
    int lda1, int K1w,
    const uint32_t* __restrict__ A2h, const uint32_t* __restrict__ A2l,
    int lda2,
    const uint32_t* __restrict__ Wh, const uint32_t* __restrict__ Wl, int Kw,
    const float* __restrict__ bias,
    float* __restrict__ C, int ldc,
    uint32_t* __restrict__ Ch, uint32_t* __restrict__ Cl,
    int N)
{
    extern __shared__ uint32_t sm[];
    gemm_core(A1h, A1l, lda1, K1w, A2h, A2l, lda2, Wh, Wl, Kw, bias,
              C, ldc, Ch, Cl, N, blockIdx.x * 128, blockIdx.y * 128, smem_u32(sm));
}

// ---------------- frontend ----------------
__global__ __launch_bounds__(256) void frontend_kernel(
    const float* __restrict__ x,
    const float* __restrict__ conv_w, const float* __restrict__ conv_b,
    const float* __restrict__ bn1_g, const float* __restrict__ bn1_b,
    const float* __restrict__ bn1_rm, const float* __restrict__ bn1_rv,
    const float* __restrict__ comp_w, const float* __restrict__ comp_b,
    const float* __restrict__ proj_w, const float* __restrict__ proj_b,
    float* __restrict__ combined)
{
    __shared__ float xs[TT][17];
    __shared__ float cw[24 * 9 * 3];
    __shared__ float cbias[24], cscale[24], cshift[24];
    __shared__ float cpw[20 * 8], cpb[20];
    __shared__ float feat[TS][44];

    const int b = blockIdx.x;
    const int tid = threadIdx.x;
    const float* xb = x + (size_t)b * TT * 17;

    for (int i = tid; i < TT * 17; i += 256) xs[i / 17][i % 17] = xb[i];
    for (int i = tid; i < 648; i += 256) cw[i] = conv_w[i];
    if (tid < 24) {
        cbias[tid] = conv_b[tid];
        float s = bn1_g[tid] * rsqrtf(bn1_rv[tid] + EPS);
        cscale[tid] = s;
        cshift[tid] = bn1_b[tid] - bn1_rm[tid] * s;
    }
    for (int i = tid; i < 160; i += 256) cpw[i] = comp_w[i];
    if (tid < 20) cpb[tid] = comp_b[tid];
    __syncthreads();

    for (int idx = tid; idx < 24 * TS; idx += 256) {
        int o = idx % 24, th = idx / 24;
        float mx = -1e30f;
        #pragma unroll
        for (int s = 0; s < 2; s++) {
            int t = th * 2 + s;
            float acc = cbias[o];
            #pragma unroll
            for (int k = 0; k < 3; k++) {
                int tt = t + k - 1;
                if (tt >= 0 && tt < TT) {
                    #pragma unroll
                    for (int i2 = 0; i2 < 9; i2++)
                        acc += xs[tt][i2] * cw[o * 27 + i2 * 3 + k];
                }
            }
            acc = fmaxf(acc, 0.0f);
            acc = acc * cscale[o] + cshift[o];
            mx = fmaxf(mx, acc);
        }
        feat[th][o] = mx;
    }
    for (int idx = tid; idx < TS * 20; idx += 256) {
        int j = idx % 20, t = idx / 20;
        float acc = cpb[j];
        #pragma unroll
        for (int i2 = 0; i2 < 8; i2++) acc += xs[t][9 + i2] * cpw[j * 8 + i2];
        feat[t][24 + j] = fmaxf(acc, 0.0f);
    }
    __syncthreads();

    for (int hh = tid; hh < H; hh += 256) {
        float w[44];
        #pragma unroll
        for (int f = 0; f < 44; f++) w[f] = proj_w[hh * 44 + f];
        float pb = proj_b[hh];
        for (int t = 0; t < TS; t++) {
            float acc = pb;
            #pragma unroll
            for (int f = 0; f < 44; f++) acc += feat[t][f] * w[f];
            combined[((size_t)b * TS + t) * H + hh] = acc;
        }
    }
}

// ---------------- gate: warp per batch row ----------------
__device__ __forceinline__ float sigm(float v) { return 1.0f / (1.0f + expf(-v)); }

__device__ __forceinline__ void warp_ln(const float* v, float& mu, float& rs) {
    float s = 0.0f, q = 0.0f;
    #pragma unroll
    for (int i = 0; i < 16; i++) { s += v[i]; q += v[i] * v[i]; }
    #pragma unroll
    for (int o = 16; o > 0; o >>= 1) {
        s += __shfl_xor_sync(0xffffffffu, s, o);
        q += __shfl_xor_sync(0xffffffffu, q, o);
    }
    mu = s * (1.0f / 512.0f);
    rs = rsqrtf(q * (1.0f / 512.0f) - mu * mu + EPS);
}

__global__ __launch_bounds__(256) void gate_kernel(
    const float* __restrict__ G,
    uint32_t* __restrict__ hH, uint32_t* __restrict__ hL,
    float* __restrict__ c,
    const float* __restrict__ ret,
    const float* __restrict__ eg, const float* __restrict__ ebb,
    const float* __restrict__ lg, const float* __restrict__ lbb,
    uint32_t* __restrict__ soH, uint32_t* __restrict__ soL)
{
    const int wid = threadIdx.x >> 5, lid = threadIdx.x & 31;
    const size_t b = (size_t)blockIdx.x * 8 + wid;
    const float* g = G + b * NG;
    float* crow = c + b * H;

    float o_[16], cn_[16];
    #pragma unroll
    for (int j = 0; j < 4; j++) {
        const int col = lid * 4 + j * 128;
        float4 vf = __ldcs((const float4*)(g + 0 * H + col));
        float4 vi = __ldcs((const float4*)(g + 1 * H + col));
        float4 vo = __ldcs((const float4*)(g + 2 * H + col));
        float4 vc = __ldcs((const float4*)(g + 3 * H + col));
        float4 vm = __ldcs((const float4*)(g + 4 * H + col));
        float4 cp = *(const float4*)(crow + col);
        float4 rr = *(const float4*)(ret + col);
        float bf[4], bi[4], bo[4], bc[4], bm[4], bp[4], br[4];
        *(float4*)bf = vf; *(float4*)bi = vi; *(float4*)bo = vo;
        *(float4*)bc = vc; *(float4*)bm = vm; *(float4*)bp = cp; *(float4*)br = rr;
        #pragma unroll
        for (int e = 0; e < 4; e++) {
            float f = sigm(bf[e]), iv = sigm(bi[e]), m = sigm(bm[e]);
            float ccv = tanhf(bc[e]);
            float cpv = bp[e], rv = br[e];
            float cn = f * cpv + iv * ccv;
            cn = cn * rv + (1.0f - rv) * cpv;
            cn = m * cn + (1.0f - m) * cpv;
            cn_[j * 4 + e] = cn;
            o_[j * 4 + e] = sigm(bo[e]);
        }
    }

    float mu1, rs1;
    warp_ln(o_, mu1, rs1);
    float u_[16];
    #pragma unroll
    for (int j = 0; j < 4; j++) {
        const int col = lid * 4 + j * 128;
        float4 ge = *(const float4*)(eg + col);
        float4 be = *(const float4*)(ebb + col);
        float g_[4], b_[4];
        *(float4*)g_ = ge; *(float4*)b_ = be;
        #pragma unroll
        for (int e = 0; e < 4; e++) {
            float on = (o_[j * 4 + e] - mu1) * rs1 * g_[e] + b_[e];
            u_[j * 4 + e] = sigm(on) * tanhf(cn_[j * 4 + e]);
        }
    }

    float mu2, rs2;
    warp_ln(u_, mu2, rs2);
    #pragma unroll
    for (int j = 0; j < 4; j++) {
        const int col = lid * 4 + j * 128;
        float4 gl = *(const float4*)(lg + col);
        float4 bl = *(const float4*)(lbb + col);
        float g_[4], b_[4], hn[4], cv[4];
        *(float4*)g_ = gl; *(float4*)b_ = bl;
        #pragma unroll
        for (int e = 0; e < 4; e++) {
            hn[e] = (u_[j * 4 + e] - mu2) * rs2 * g_[e] + b_[e];
            cv[e] = cn_[j * 4 + e];
        }
        *(float4*)(crow + col) = *(float4*)cv;
        float h0 = bf_hi(hn[0]), h1 = bf_hi(hn[1]), h2 = bf_hi(hn[2]), h3 = bf_hi(hn[3]);
        uint2 wh, wl;
        wh.x = pack_bf(h0, h1);              wh.y = pack_bf(h2, h3);
        wl.x = pack_bf(hn[0] - h0, hn[1] - h1);
        wl.y = pack_bf(hn[2] - h2, hn[3] - h3);
        *(uint2*)(hH + b * HW + (col >> 1)) = wh;
        *(uint2*)(hL + b * HW + (col >> 1)) = wl;
        if (soH) {
            *(uint2*)(soH + b * TS * HW + (col >> 1)) = wh;
            *(uint2*)(soL + b * TS * HW + (col >> 1)) = wl;
        }
    }
}

// ---------------- last-query attention ----------------
__global__ __launch_bounds__(128) void attn_kernel(
    const float* __restrict__ q,
    const float* __restrict__ kv,
    uint32_t* __restrict__ attH, uint32_t* __restrict__ attL)
{
    __shared__ float qs[DH];
    __shared__ float sc[TS];
    const int b = blockIdx.x, hd = blockIdx.y;
    const int tid = threadIdx.x;

    qs[tid] = q[(size_t)b * H + hd * DH + tid];
    __syncthreads();

    if (tid < TS) {
        const float* kr = kv + ((size_t)b * TS + tid) * K2H + hd * DH;
        float s = 0.0f;
        #pragma unroll 16
        for (int d = 0; d < DH; d++) s += qs[d] * kr[d];
        sc[tid] = s * 0.08838834764831845f;
    }
    __syncthreads();

    float mx = -1e30f;
    #pragma unroll
    for (int t = 0; t < TS; t++) mx = fmaxf(mx, sc[t]);
    float p[TS], ssum = 0.0f;
    #pragma unroll
    for (int t = 0; t < TS; t++) { p[t] = expf(sc[t] - mx); ssum += p[t]; }
    float inv = 1.0f / ssum;

    float acc = 0.0f;
    #pragma unroll
    for (int t = 0; t < TS; t++)
        acc += p[t] * kv[((size_t)b * TS + t) * K2H + H + hd * DH + tid];
    float v = acc * inv;

    float pv = __shfl_down_sync(0xffffffffu, v, 1);
    if (!(tid & 1)) {
        float h0 = bf_hi(v), h1 = bf_hi(pv);
        const size_t w = (size_t)b * HW + hd * (DH / 2) + (tid >> 1);
        attH[w] = pack_bf(h0, h1);
        attL[w] = pack_bf(v - h0, pv - h1);
    }
}

// ---------------- bn2 + output head ----------------
__global__ __launch_bounds__(256) void head_kernel(
    const float* __restrict__ latent,
    const float* __restrict__ bn2_g, const float* __restrict__ bn2_b,
    const float* __restrict__ bn2_rm, const float* __restrict__ bn2_rv,
    const float* __restrict__ out_w, const float* __restrict__ out_b,
    float* __restrict__ out)
{
    __shared__ float lw[OUT * LAT];
    __shared__ float ls[16][LAT];
    __shared__ float scale[LAT], shift[LAT];
    const int b0 = blockIdx.x * 16;
    const int tid = threadIdx.x;

    if (tid < LAT) {
        float s = bn2_g[tid] * rsqrtf(bn2_rv[tid] + EPS);
        scale[tid] = s;
        shift[tid] = bn2_b[tid] - bn2_rm[tid] * s;
    }
    for (int i = tid; i < OUT * LAT; i += 256) lw[i] = out_w[i];
    __syncthreads();

    for (int i = tid; i < 16 * LAT; i += 256) {
        int r = i / LAT, j = i % LAT;
        ls[r][j] = latent[(size_t)(b0 + r) * LAT + j] * scale[j] + shift[j];
    }
    __syncthreads();

    for (int idx = tid; idx < 16 * OUT; idx += 256) {
        int r = idx / OUT, o = idx % OUT;
        float acc = out_b[o];
        #pragma unroll 16
        for (int j = 0; j < LAT; j++) acc += ls[r][j] * lw[o * LAT + j];
        out[(size_t)(b0 + r) * OUT + o] = acc;
    }
}

// ---------------- host launch ----------------
extern "C" void kernel_launch(void* const* d_in, const int* in_sizes, int n_in,
                              void* d_out, int out_size)
{
    const float* x        = (const float*)d_in[0];
    const float* conv1_w  = (const float*)d_in[1];
    const float* conv1_b  = (const float*)d_in[2];
    const float* bn1_g    = (const float*)d_in[3];
    const float* bn1_b    = (const float*)d_in[4];
    const float* bn1_rm   = (const float*)d_in[5];
    const float* bn1_rv   = (const float*)d_in[6];
    const float* comp_w   = (const float*)d_in[7];
    const float* comp_b   = (const float*)d_in[8];
    const float* proj_w   = (const float*)d_in[9];
    const float* proj_b   = (const float*)d_in[10];
    const float* gates_w  = (const float*)d_in[11];
    const float* gates_b  = (const float*)d_in[12];
    const float* retention= (const float*)d_in[13];
    const float* expln_g  = (const float*)d_in[14];
    const float* expln_b  = (const float*)d_in[15];
    const float* ln_g     = (const float*)d_in[16];
    const float* ln_b     = (const float*)d_in[17];
    const float* attn_in_w= (const float*)d_in[18];
    const float* attn_in_b= (const float*)d_in[19];
    const float* attn_out_w=(const float*)d_in[20];
    const float* attn_out_b=(const float*)d_in[21];
    const float* bneck_w  = (const float*)d_in[22];
    const float* bneck_b  = (const float*)d_in[23];
    const float* bn2_g    = (const float*)d_in[24];
    const float* bn2_b    = (const float*)d_in[25];
    const float* bn2_rm   = (const float*)d_in[26];
    const float* bn2_rv   = (const float*)d_in[27];
    const float* out_w    = (const float*)d_in[28];
    const float* out_b    = (const float*)d_in[29];
    float* out = (float*)d_out;

    // one-time stream/event resources (host-side only; no device allocation)
    static cudaStream_t s1 = nullptr, s2 = nullptr;
    static cudaEvent_t ev0[TS], evg1[TS], evs1[TS], evend, evkv;
    if (!s1) {
        int loPrio = 0, hiPrio = 0;
        cudaDeviceGetStreamPriorityRange(&loPrio, &hiPrio);
        cudaStreamCreateWithPriority(&s1, cudaStreamNonBlocking, loPrio);
        cudaStreamCreateWithPriority(&s2, cudaStreamNonBlocking, loPrio);
        for (int i = 0; i < TS; i++) {
            cudaEventCreateWithFlags(&ev0[i], cudaEventDisableTiming);
            cudaEventCreateWithFlags(&evg1[i], cudaEventDisableTiming);
            cudaEventCreateWithFlags(&evs1[i], cudaEventDisableTiming);
        }
        cudaEventCreateWithFlags(&evend, cudaEventDisableTiming);
        cudaEventCreateWithFlags(&evkv, cudaEventDisableTiming);
        cudaFuncSetAttribute(gemm_bf16, cudaFuncAttributeMaxDynamicSharedMemorySize,
                             GEMM_SMEM_BYTES);
    }

    float *combined, *G0, *G1, *c, *kv, *q, *lat;
    uint32_t *combH, *combL, *seqH, *seqL, *hH, *hL, *attH, *attL, *finH, *finL, *Wh, *Wl;
    cudaGetSymbolAddress((void**)&combined, d_combined);
    cudaGetSymbolAddress((void**)&G0,       d_G0);
    cudaGetSymbolAddress((void**)&G1,       d_G1);
    cudaGetSymbolAddress((void**)&c,        d_c);
    cudaGetSymbolAddress((void**)&kv,       d_kv);
    cudaGetSymbolAddress((void**)&q,        d_q);
    cudaGetSymbolAddress((void**)&lat,      d_lat);
    cudaGetSymbolAddress((void**)&combH,    d_combH);
    cudaGetSymbolAddress((void**)&combL,    d_combL);
    cudaGetSymbolAddress((void**)&seqH,     d_seqH);
    cudaGetSymbolAddress((void**)&seqL,     d_seqL);
    cudaGetSymbolAddress((void**)&hH,       d_hH);
    cudaGetSymbolAddress((void**)&hL,       d_hL);
    cudaGetSymbolAddress((void**)&attH,     d_attH);
    cudaGetSymbolAddress((void**)&attL,     d_attL);
    cudaGetSymbolAddress((void**)&finH,     d_finH);
    cudaGetSymbolAddress((void**)&finL,     d_finL);
    cudaGetSymbolAddress((void**)&Wh,       d_Wh);
    cudaGetSymbolAddress((void**)&Wl,       d_Wl);

    uint32_t* h0H_[2] = { hH, hH + (size_t)B * HW };
    uint32_t* h0L_[2] = { hL, hL + (size_t)B * HW };
    uint32_t* h1H = hH + (size_t)2 * B * HW;
    uint32_t* h1L = hL + (size_t)2 * B * HW;
    float* c0 = c;
    float* c1 = c + (size_t)B * H;

    zero3_kernel<<<2048, 512>>>(c, 2 * B * H,
                                (float*)hH, 3 * B * HW,
                                (float*)hL, 3 * B * HW);
    frontend_kernel<<<B, 256>>>(x, conv1_w, conv1_b, bn1_g, bn1_b, bn1_rm, bn1_rv,
                                comp_w, comp_b, proj_w, proj_b, combined);
    split5_kernel<<<8192, 256>>>(
        gates_w,    Wh + OFF_W0,   Wl + OFF_W0,   NG * K2H,
        combined,   combH,         combL,         B * TS * H / 2,
        attn_in_w,  Wh + OFF_AIN,  Wl + OFF_AIN,  3 * H * H / 2,
        attn_out_w, Wh + OFF_AOUT, Wl + OFF_AOUT, H * H / 2,
        bneck_w,    Wh + OFF_BNK,  Wl + OFF_BNK,  LAT * H / 2);

    const float* gb0 = gates_b;
    const float* gb1 = gates_b + NG;
    dim3 gemm_grid(B / 128, NG / 128);   // 640 CTAs

    // prologue: G0(0) = [comb(0) | h0(zero)] @ W0 + gb0
    gemm_bf16<<<gemm_grid, 256, GEMM_SMEM_BYTES>>>(
        combH, combL, TS * HW, HW, h0H_[1], h0L_[1], HW,
        Wh + OFF_W0, Wl + OFF_W0, 2 * HW, gb0, G0, NG, nullptr, nullptr, NG);
    gate_kernel<<<B / 8, 256>>>(G0, h0H_[0], h0L_[0], c0,
                                retention, expln_g, expln_b, ln_g, ln_b,
                                nullptr, nullptr);
    cudaEventRecord(ev0[0], 0);

    // two-chain scan + interleaved kv chunks
    for (int t = 0; t < TS; t++) {
        const int p = t & 1;
        // chain 1 (s1): G1(t) = [h0(t) | h1(t-1)] @ W1 ; gate1(t) -> h1, seq(t)
        cudaStreamWaitEvent(s1, ev0[t], 0);
        gemm_bf16<<<gemm_grid, 256, GEMM_SMEM_BYTES, s1>>>(
            h0H_[p], h0L_[p], HW, HW, h1H, h1L, HW,
            Wh + OFF_W1, Wl + OFF_W1, 2 * HW, gb1, G1, NG, nullptr, nullptr, NG);
        cudaEventRecord(evg1[t], s1);
        gate_kernel<<<B / 8, 256, 0, s1>>>(
            G1, h1H, h1L, c1,
            retention + H, expln_g + H, expln_b + H, ln_g + H, ln_b + H,
            seqH + (size_t)t * HW, seqL + (size_t)t * HW);
        cudaEventRecord(evs1[t], s1);

        // kv chunk for timestep t (s2): seq(t) @ W_kv -> kv rows (b*TS+t)
        cudaStreamWaitEvent(s2, evs1[t], 0);
        gemm_bf16<<<dim3(B / 128, K2H / 128), 256, GEMM_SMEM_BYTES, s2>>>(
            seqH + (size_t)t * HW, seqL + (size_t)t * HW, TS * HW, HW,
            seqH, seqL, HW,
            Wh + OFF_AIN + (size_t)H * H / 2, Wl + OFF_AIN + (size_t)H * H / 2, HW,
            attn_in_b + H, kv + (size_t)t * K2H, TS * K2H, nullptr, nullptr, K2H);

        // chain 0 (default, high pref): G0(t+1) ; gate0(t+1) -> h0[p^1]
        if (t + 1 < TS) {
            gemm_bf16<<<gemm_grid, 256, GEMM_SMEM_BYTES>>>(
                combH + (size_t)(t + 1) * HW, combL + (size_t)(t + 1) * HW, TS * HW, HW,
                h0H_[p], h0L_[p], HW,
                Wh + OFF_W0, Wl + OFF_W0, 2 * HW, gb0, G0, NG, nullptr, nullptr, NG);
            if (t >= 1) cudaStreamWaitEvent(0, evg1[t - 1], 0);   // h0[p^1] WAR guard
            gate_kernel<<<B / 8, 256>>>(G0, h0H_[p ^ 1], h0L_[p ^ 1], c0,
                                        retention, expln_g, expln_b, ln_g, ln_b,
                                        nullptr, nullptr);
            cudaEventRecord(ev0[t + 1], 0);
        }
    }
    cudaEventRecord(evend, s1);
    cudaEventRecord(evkv, s2);
    cudaStreamWaitEvent(0, evend, 0);
    cudaStreamWaitEvent(0, evkv, 0);

    // q at last timestep
    gemm_bf16<<<dim3(B / 128, H / 128), 256, GEMM_SMEM_BYTES>>>(
        seqH + (size_t)(TS - 1) * HW, seqL + (size_t)(TS - 1) * HW, TS * HW, HW,
        seqH, seqL, HW,
        Wh + OFF_AIN, Wl + OFF_AIN, HW, attn_in_b, q, H, nullptr, nullptr, H);
    attn_kernel<<<dim3(B, NH), 128>>>(q, kv, attH, attL);
    gemm_bf16<<<dim3(B / 128, H / 128), 256, GEMM_SMEM_BYTES>>>(
        attH, attL, HW, HW, attH, attL, HW,
        Wh + OFF_AOUT, Wl + OFF_AOUT, HW, attn_out_b, nullptr, H, finH, finL, H);
    gemm_bf16<<<dim3(B / 128, LAT / 128), 256, GEMM_SMEM_BYTES>>>(
        finH, finL, HW, HW, finH, finL, HW,
        Wh + OFF_BNK, Wl + OFF_BNK, HW, bneck_b, lat, LAT, nullptr, nullptr, LAT);
    head_kernel<<<B / 16, 256>>>(lat, bn2_g, bn2_b, bn2_rm, bn2_rv, out_w, out_b, out);
}

// round 17
// speedup vs baseline: 1.0041x; 1.0041x over previous
#include <cuda_runtime.h>
#include <cuda_bf16.h>
#include <cstdint>
#include <cstddef>

#define EPS 1e-5f

// ---------------- problem constants ----------------
#define B   4096
#define TT  60
#define TS  30
#define H   512
#define LAT 128
#define OUT 14
#define NH  4
#define DH  128
#define NG  2560
#define K2H 1024

// ---------------- device scratch ----------------
__device__ float d_G0      [(size_t)B * NG];
__device__ float d_G1      [(size_t)B * NG];
__device__ float d_c       [(size_t)2 * B * H];
__device__ float d_kv      [(size_t)B * TS * K2H];
__device__ float d_q       [(size_t)B * H];
__device__ float d_lat     [(size_t)B * LAT];

#define HW  256
__device__ uint32_t d_combH[(size_t)B * TS * HW];
__device__ uint32_t d_combL[(size_t)B * TS * HW];
__device__ uint32_t d_seqH [(size_t)B * TS * HW];
__device__ uint32_t d_seqL [(size_t)B * TS * HW];
__device__ uint32_t d_hH   [(size_t)3 * B * HW];   // h0a | h0b | h1
__device__ uint32_t d_hL   [(size_t)3 * B * HW];
__device__ uint32_t d_attH [(size_t)B * HW];
__device__ uint32_t d_attL [(size_t)B * HW];
__device__ uint32_t d_finH [(size_t)B * HW];
__device__ uint32_t d_finL [(size_t)B * HW];

#define OFF_W0   0
#define OFF_W1   1310720
#define OFF_AIN  2621440
#define OFF_AOUT 3014656
#define OFF_BNK  3145728
#define W_WORDS  3178496
__device__ uint32_t d_Wh[(size_t)W_WORDS];
__device__ uint32_t d_Wl[(size_t)W_WORDS];

// ---------------- helpers ----------------
__device__ __forceinline__ uint32_t pack_bf(float a, float b) {
    __nv_bfloat162 t = __floats2bfloat162_rn(a, b);
    return *reinterpret_cast<uint32_t*>(&t);
}
__device__ __forceinline__ float bf_hi(float x) {
    return __bfloat162float(__float2bfloat16_rn(x));
}
__device__ __forceinline__ uint32_t smem_u32(const void* p) {
    uint32_t a;
    asm("{ .reg .u64 t; cvta.to.shared.u64 t, %1; cvt.u32.u64 %0, t; }" : "=r"(a) : "l"(p));
    return a;
}

#define MMA16(d, a, b) \
    asm volatile( \
        "mma.sync.aligned.m16n8k16.row.col.f32.bf16.bf16.f32 " \
        "{%0,%1,%2,%3}, {%4,%5,%6,%7}, {%8,%9}, {%0,%1,%2,%3};" \
        : "+f"((d)[0]), "+f"((d)[1]), "+f"((d)[2]), "+f"((d)[3]) \
        : "r"((a)[0]), "r"((a)[1]), "r"((a)[2]), "r"((a)[3]), \
          "r"((b)[0]), "r"((b)[1]))

#define LDSM4(v, addr) \
    asm volatile("ldmatrix.sync.aligned.m8n8.x4.shared.b16 {%0,%1,%2,%3}, [%4];" \
        : "=r"((v)[0]), "=r"((v)[1]), "=r"((v)[2]), "=r"((v)[3]) : "r"(addr))

#define CP16(dst, src) \
    asm volatile("cp.async.cg.shared.global [%0], [%1], 16;" :: "r"(dst), "l"(src))
#define CPCOMMIT() asm volatile("cp.async.commit_group;" ::: "memory")
#define CPWAIT1()  asm volatile("cp.async.wait_group 1;" ::: "memory")

#define STG_WORDS 8192
#define GEMM_SMEM_BYTES (3 * STG_WORDS * 4)

// ---------------- fused zero init ----------------
__global__ void zero3_kernel(float* __restrict__ p0, int n0,
                             float* __restrict__ p1, int n1,
                             float* __restrict__ p2, int n2) {
    int i = blockIdx.x * blockDim.x + threadIdx.x;
    int stride = gridDim.x * blockDim.x;
    for (int j = i; j < n0; j += stride) p0[j] = 0.0f;
    for (int j = i; j < n1; j += stride) p1[j] = 0.0f;
    for (int j = i; j < n2; j += stride) p2[j] = 0.0f;
}

// ---------------- bf16 hi/lo packed split (weights only) ----------------
__device__ __forceinline__ void split_range(const float* __restrict__ src,
                                            uint32_t* __restrict__ hi,
                                            uint32_t* __restrict__ lo,
                                            int nwords, int i, int stride) {
    for (; i < nwords; i += stride) {
        float2 v = *(const float2*)(src + 2 * (size_t)i);
        float h0 = bf_hi(v.x), h1 = bf_hi(v.y);
        hi[i] = pack_bf(h0, h1);
        lo[i] = pack_bf(v.x - h0, v.y - h1);
    }
}
__global__ void split4_kernel(
    const float* __restrict__ s0, uint32_t* __restrict__ h0, uint32_t* __restrict__ l0, int n0,
    const float* __restrict__ s1, uint32_t* __restrict__ h1, uint32_t* __restrict__ l1, int n1,
    const float* __restrict__ s2, uint32_t* __restrict__ h2, uint32_t* __restrict__ l2, int n2,
    const float* __restrict__ s3, uint32_t* __restrict__ h3, uint32_t* __restrict__ l3, int n3) {
    int i = blockIdx.x * blockDim.x + threadIdx.x;
    int stride = gridDim.x * blockDim.x;
    split_range(s0, h0, l0, n0, i, stride);
    split_range(s1, h1, l1, n1, i, stride);
    split_range(s2, h2, l2, n2, i, stride);
    split_range(s3, h3, l3, n3, i, stride);
}

// ================= bf16x3 GEMM core (128x128 tile, 2 CTA/SM; two A sources) ========
__device__ __forceinline__ void gemm_core(
    const uint32_t* __restrict__ A1h, const uint32_t* __restrict__ A1l,
    int lda1, int K1w,
    const uint32_t* __restrict__ A2h, const uint32_t* __restrict__ A2l,
    int lda2,
    const uint32_t* __restrict__ Wh, const uint32_t* __restrict__ Wl, int Kw,
    const float* __restrict__ bias,
    float* __restrict__ C, int ldc,
    uint32_t* __restrict__ Ch, uint32_t* __restrict__ Cl,
    int N, int m0, int n0, uint32_t smb)
{
    const int tid = threadIdx.x;
    const int wid = tid >> 5, lane = tid & 31;
    const int g = lane >> 2, t4 = lane & 3;
    const int warp_m = wid >> 2, warp_n = wid & 3;

    const int r = tid >> 1, half = tid & 1;
    const int wb = half * 8;
    const int swz = ((r >> 1) & 3) << 2;
    const int so0 = r * 16 + ((wb) ^ swz);
    const int so1 = r * 16 + ((wb + 4) ^ swz);

    const int a_r = lane & 15;
    const int a_k = (lane >> 4) << 2;
    int aoff[4], aswz[4];
    #pragma unroll
    for (int tm = 0; tm < 4; tm++) {
        const int row = warp_m * 64 + tm * 16 + a_r;
        aoff[tm] = row * 16;
        aswz[tm] = ((row >> 1) & 3) << 2;
    }
    const int b_r = (lane & 7) + ((lane >> 4) << 3);
    const int b_k = ((lane >> 3) & 1) << 2;
    int boff[2], bswz[2];
    #pragma unroll
    for (int tp = 0; tp < 2; tp++) {
        const int row = warp_n * 32 + tp * 16 + b_r;
        boff[tp] = row * 16;
        bswz[tp] = ((row >> 1) & 3) << 2;
    }

    float acc[4][4][4];
    #pragma unroll
    for (int i = 0; i < 4; i++)
        #pragma unroll
        for (int j = 0; j < 4; j++)
            #pragma unroll
            for (int e = 0; e < 4; e++) acc[i][j][e] = 0.0f;

    const int NKB = Kw / 16;

    auto issue = [&](int kb, int stage) {
        const int kbw = kb * 16 + wb;
        const uint32_t *ah, *al;
        if (kbw < K1w) {
            ah = A1h + (size_t)(m0 + r) * lda1 + kbw;
            al = A1l + (size_t)(m0 + r) * lda1 + kbw;
        } else {
            ah = A2h + (size_t)(m0 + r) * lda2 + (kbw - K1w);
            al = A2l + (size_t)(m0 + r) * lda2 + (kbw - K1w);
        }
        const uint32_t* bh = Wh + (size_t)(n0 + r) * Kw + kbw;
        const uint32_t* bl = Wl + (size_t)(n0 + r) * Kw + kbw;
        const uint32_t sb = smb + (uint32_t)(stage * STG_WORDS) * 4;
        CP16(sb + so0 * 4, ah);                 CP16(sb + so1 * 4, ah + 4);
        CP16(sb + (2048 + so0) * 4, al);        CP16(sb + (2048 + so1) * 4, al + 4);
        CP16(sb + (4096 + so0) * 4, bh);        CP16(sb + (4096 + so1) * 4, bh + 4);
        CP16(sb + (6144 + so0) * 4, bl);        CP16(sb + (6144 + so1) * 4, bl + 4);
    };

    issue(0, 0); CPCOMMIT();
    issue(1, 1); CPCOMMIT();

    for (int kb = 0; kb < NKB; kb++) {
        CPWAIT1();
        __syncthreads();
        const uint32_t sbase = smb + (uint32_t)((kb % 3) * STG_WORDS) * 4;

        #pragma unroll
        for (int kc = 0; kc < 2; kc++) {
            const int akw = kc * 8 + a_k;
            const int bkw = kc * 8 + b_k;
            uint32_t Bh[2][4], Bl[2][4];
            #pragma unroll
            for (int tp = 0; tp < 2; tp++) {
                const uint32_t bd = sbase + (uint32_t)(4096 + boff[tp] + (bkw ^ bswz[tp])) * 4;
                LDSM4(Bh[tp], bd);
                LDSM4(Bl[tp], bd + 2048 * 4);
            }
            #pragma unroll
            for (int tm = 0; tm < 4; tm++) {
                uint32_t Ahf[4], Alf[4];
                const uint32_t ad = sbase + (uint32_t)(aoff[tm] + (akw ^ aswz[tm])) * 4;
                LDSM4(Ahf, ad);
                LDSM4(Alf, ad + 2048 * 4);
                #pragma unroll
                for (int tn = 0; tn < 4; tn++) {
                    uint32_t* bh = &Bh[tn >> 1][(tn & 1) * 2];
                    uint32_t* bl = &Bl[tn >> 1][(tn & 1) * 2];
                    MMA16(acc[tm][tn], Ahf, bh);
                    MMA16(acc[tm][tn], Ahf, bl);
                    MMA16(acc[tm][tn], Alf, bh);
                }
            }
        }
        if (kb + 2 < NKB) issue(kb + 2, (kb + 2) % 3);
        CPCOMMIT();
    }

    const int Nw = N >> 1;
    #pragma unroll
    for (int tm = 0; tm < 4; tm++) {
        const int row0 = m0 + warp_m * 64 + tm * 16 + g;
        #pragma unroll
        for (int tn = 0; tn < 4; tn++) {
            const int col = n0 + warp_n * 32 + tn * 8 + t4 * 2;
            const float b0 = bias[col], b1 = bias[col + 1];
            const float v00 = acc[tm][tn][0] + b0, v01 = acc[tm][tn][1] + b1;
            const float v10 = acc[tm][tn][2] + b0, v11 = acc[tm][tn][3] + b1;
            if (C) {
                __stcs((float2*)(C + (size_t)row0 * ldc + col), make_float2(v00, v01));
                __stcs((float2*)(C + (size_t)(row0 + 8) * ldc + col), make_float2(v10, v11));
            }
            if (Ch) {
                const int w = (col >> 1);
                float h00 = bf_hi(v00), h01 = bf_hi(v01);
                float h10 = bf_hi(v10), h11 = bf_hi(v11);
                Ch[(size_t)row0 * Nw + w]       = pack_bf(h00, h01);
                Cl[(size_t)row0 * Nw + w]       = pack_bf(v00 - h00, v01 - h01);
                Ch[(size_t)(row0 + 8) * Nw + w] = pack_bf(h10, h11);
                Cl[(size_t)(row0 + 8) * Nw + w] = pack_bf(v10 - h10, v11 - h11);
            }
        }
    }
}

__global__ __launch_bounds__(256, 2) void gemm_bf16(
    const uint32_t* __restrict__ A1h, const uint32_t* __restrict__ A1l,
    int lda1, int K1w,
    const uint32_t* __restrict__ A2h, const uint32_t* __restrict__ A2l,
    int lda2,
    const uint32_t* __restrict__ Wh, const uint32_t* __restrict__ Wl, int Kw,
    const float* __restrict__ bias,
    float* __restrict__ C, int ldc,
    uint32_t* __restrict__ Ch, uint32_t* __restrict__ Cl,
    int N)
{
    extern __shared__ uint32_t sm[];
    gemm_core(A1h, A1l, lda1, K1w, A2h, A2l, lda2, Wh, Wl, Kw, bias,
              C, ldc, Ch, Cl, N, blockIdx.x * 128, blockIdx.y * 128, smem_u32(sm));
}

// ---------------- frontend: conv+bn+pool+comp+projection, packed bf16 output -----
__global__ __launch_bounds__(256) void frontend_kernel(
    const float* __restrict__ x,
    const float* __restrict__ conv_w, const float* __restrict__ conv_b,
    const float* __restrict__ bn1_g, const float* __restrict__ bn1_b,
    const float* __restrict__ bn1_rm, const float* __restrict__ bn1_rv,
    const float* __restrict__ comp_w, const float* __restrict__ comp_b,
    const float* __restrict__ proj_w, const float* __restrict__ proj_b,
    uint32_t* __restrict__ combH, uint32_t* __restrict__ combL)
{
    __shared__ float xs[TT][17];
    __shared__ float cw[24 * 9 * 3];
    __shared__ float cbias[24], cscale[24], cshift[24];
    __shared__ float cpw[20 * 8], cpb[20];
    __shared__ float feat[TS][44];

    const int b = blockIdx.x;
    const int tid = threadIdx.x;
    const float* xb = x + (size_t)b * TT * 17;

    for (int i = tid; i < TT * 17; i += 256) xs[i / 17][i % 17] = xb[i];
    for (int i = tid; i < 648; i += 256) cw[i] = conv_w[i];
    if (tid < 24) {
        cbias[tid] = conv_b[tid];
        float s = bn1_g[tid] * rsqrtf(bn1_rv[tid] + EPS);
        cscale[tid] = s;
        cshift[tid] = bn1_b[tid] - bn1_rm[tid] * s;
    }
    for (int i = tid; i < 160; i += 256) cpw[i] = comp_w[i];
    if (tid < 20) cpb[tid] = comp_b[tid];
    __syncthreads();

    for (int idx = tid; idx < 24 * TS; idx += 256) {
        int o = idx % 24, th = idx / 24;
        float mx = -1e30f;
        #pragma unroll
        for (int s = 0; s < 2; s++) {
            int t = th * 2 + s;
            float acc = cbias[o];
            #pragma unroll
            for (int k = 0; k < 3; k++) {
                int tt = t + k - 1;
                if (tt >= 0 && tt < TT) {
                    #pragma unroll
                    for (int i2 = 0; i2 < 9; i2++)
                        acc += xs[tt][i2] * cw[o * 27 + i2 * 3 + k];
                }
            }
            acc = fmaxf(acc, 0.0f);
            acc = acc * cscale[o] + cshift[o];
            mx = fmaxf(mx, acc);
        }
        feat[th][o] = mx;
    }
    for (int idx = tid; idx < TS * 20; idx += 256) {
        int j = idx % 20, t = idx / 20;
        float acc = cpb[j];
        #pragma unroll
        for (int i2 = 0; i2 < 8; i2++) acc += xs[t][9 + i2] * cpw[j * 8 + i2];
        feat[t][24 + j] = fmaxf(acc, 0.0f);
    }
    __syncthreads();

    // projection: thread handles h pair (2*w, 2*w+1); packed hi/lo output
    {
        const int w = tid;                    // 0..255 word index
        float w0[44], w1[44];
        #pragma unroll
        for (int f = 0; f < 44; f++) {
            w0[f] = proj_w[(2 * w) * 44 + f];
            w1[f] = proj_w[(2 * w + 1) * 44 + f];
        }
        const float pb0 = proj_b[2 * w], pb1 = proj_b[2 * w + 1];
        for (int t = 0; t < TS; t++) {
            float a0 = pb0, a1 = pb1;
            #pragma unroll
            for (int f = 0; f < 44; f++) {
                const float fv = feat[t][f];
                a0 += fv * w0[f];
                a1 += fv * w1[f];
            }
            const float h0 = bf_hi(a0), h1 = bf_hi(a1);
            const size_t o = ((size_t)b * TS + t) * HW + w;
            combH[o] = pack_bf(h0, h1);
            combL[o] = pack_bf(a0 - h0, a1 - h1);
        }
    }
}

// ---------------- gate: warp per batch row ----------------
__device__ __forceinline__ float sigm(float v) { return 1.0f / (1.0f + expf(-v)); }

__device__ __forceinline__ void warp_ln(const float* v, float& mu, float& rs) {
    float s = 0.0f, q = 0.0f;
    #pragma unroll
    for (int i = 0; i < 16; i++) { s += v[i]; q += v[i] * v[i]; }
    #pragma unroll
    for (int o = 16; o > 0; o >>= 1) {
        s += __shfl_xor_sync(0xffffffffu, s, o);
        q += __shfl_xor_sync(0xffffffffu, q, o);
    }
    mu = s * (1.0f / 512.0f);
    rs = rsqrtf(q * (1.0f / 512.0f) - mu * mu + EPS);
}

__global__ __launch_bounds__(256) void gate_kernel(
    const float* __restrict__ G,
    uint32_t* __restrict__ hH, uint32_t* __restrict__ hL,
    float* __restrict__ c,
    const float* __restrict__ ret,
    const float* __restrict__ eg, const float* __restrict__ ebb,
    const float* __restrict__ lg, const float* __restrict__ lbb,
    uint32_t* __restrict__ soH, uint32_t* __restrict__ soL)
{
    const int wid = threadIdx.x >> 5, lid = threadIdx.x & 31;
    const size_t b = (size_t)blockIdx.x * 8 + wid;
    const float* g = G + b * NG;
    float* crow = c + b * H;

    float o_[16], cn_[16];
    #pragma unroll
    for (int j = 0; j < 4; j++) {
        const int col = lid * 4 + j * 128;
        float4 vf = __ldcs((const float4*)(g + 0 * H + col));
        float4 vi = __ldcs((const float4*)(g + 1 * H + col));
        float4 vo = __ldcs((const float4*)(g + 2 * H + col));
        float4 vc = __ldcs((const float4*)(g + 3 * H + col));
        float4 vm = __ldcs((const float4*)(g + 4 * H + col));
        float4 cp = *(const float4*)(crow + col);
        float4 rr = *(const float4*)(ret + col);
        float bf[4], bi[4], bo[4], bc[4], bm[4], bp[4], br[4];
        *(float4*)bf = vf; *(float4*)bi = vi; *(float4*)bo = vo;
        *(float4*)bc = vc; *(float4*)bm = vm; *(float4*)bp = cp; *(float4*)br = rr;
        #pragma unroll
        for (int e = 0; e < 4; e++) {
            float f = sigm(bf[e]), iv = sigm(bi[e]), m = sigm(bm[e]);
            float ccv = tanhf(bc[e]);
            float cpv = bp[e], rv = br[e];
            float cn = f * cpv + iv * ccv;
            cn = cn * rv + (1.0f - rv) * cpv;
            cn = m * cn + (1.0f - m) * cpv;
            cn_[j * 4 + e] = cn;
            o_[j * 4 + e] = sigm(bo[e]);
        }
    }

    float mu1, rs1;
    warp_ln(o_, mu1, rs1);
    float u_[16];
    #pragma unroll
    for (int j = 0; j < 4; j++) {
        const int col = lid * 4 + j * 128;
        float4 ge = *(const float4*)(eg + col);
        float4 be = *(const float4*)(ebb + col);
        float g_[4], b_[4];
        *(float4*)g_ = ge; *(float4*)b_ = be;
        #pragma unroll
        for (int e = 0; e < 4; e++) {
            float on = (o_[j * 4 + e] - mu1) * rs1 * g_[e] + b_[e];
            u_[j * 4 + e] = sigm(on) * tanhf(cn_[j * 4 + e]);
        }
    }

    float mu2, rs2;
    warp_ln(u_, mu2, rs2);
    #pragma unroll
    for (int j = 0; j < 4; j++) {
        const int col = lid * 4 + j * 128;
        float4 gl = *(const float4*)(lg + col);
        float4 bl = *(const float4*)(lbb + col);
        float g_[4], b_[4], hn[4], cv[4];
        *(float4*)g_ = gl; *(float4*)b_ = bl;
        #pragma unroll
        for (int e = 0; e < 4; e++) {
            hn[e] = (u_[j * 4 + e] - mu2) * rs2 * g_[e] + b_[e];
            cv[e] = cn_[j * 4 + e];
        }
        *(float4*)(crow + col) = *(float4*)cv;
        float h0 = bf_hi(hn[0]), h1 = bf_hi(hn[1]), h2 = bf_hi(hn[2]), h3 = bf_hi(hn[3]);
        uint2 wh, wl;
        wh.x = pack_bf(h0, h1);              wh.y = pack_bf(h2, h3);
        wl.x = pack_bf(hn[0] - h0, hn[1] - h1);
        wl.y = pack_bf(hn[2] - h2, hn[3] - h3);
        *(uint2*)(hH + b * HW + (col >> 1)) = wh;
        *(uint2*)(hL + b * HW + (col >> 1)) = wl;
        if (soH) {
            *(uint2*)(soH + b * TS * HW + (col >> 1)) = wh;
            *(uint2*)(soL + b * TS * HW + (col >> 1)) = wl;
        }
    }
}

// ---------------- last-query attention ----------------
__global__ __launch_bounds__(128) void attn_kernel(
    const float* __restrict__ q,
    const float* __restrict__ kv,
    uint32_t* __restrict__ attH, uint32_t* __restrict__ attL)
{
    __shared__ float qs[DH];
    __shared__ float sc[TS];
    const int b = blockIdx.x, hd = blockIdx.y;
    const int tid = threadIdx.x;

    qs[tid] = q[(size_t)b * H + hd * DH + tid];
    __syncthreads();

    if (tid < TS) {
        const float* kr = kv + ((size_t)b * TS + tid) * K2H + hd * DH;
        float s = 0.0f;
        #pragma unroll 16
        for (int d = 0; d < DH; d++) s += qs[d] * kr[d];
        sc[tid] = s * 0.08838834764831845f;
    }
    __syncthreads();

    float mx = -1e30f;
    #pragma unroll
    for (int t = 0; t < TS; t++) mx = fmaxf(mx, sc[t]);
    float p[TS], ssum = 0.0f;
    #pragma unroll
    for (int t = 0; t < TS; t++) { p[t] = expf(sc[t] - mx); ssum += p[t]; }
    float inv = 1.0f / ssum;

    float acc = 0.0f;
    #pragma unroll
    for (int t = 0; t < TS; t++)
        acc += p[t] * kv[((size_t)b * TS + t) * K2H + H + hd * DH + tid];
    float v = acc * inv;

    float pv = __shfl_down_sync(0xffffffffu, v, 1);
    if (!(tid & 1)) {
        float h0 = bf_hi(v), h1 = bf_hi(pv);
        const size_t w = (size_t)b * HW + hd * (DH / 2) + (tid >> 1);
        attH[w] = pack_bf(h0, h1);
        attL[w] = pack_bf(v - h0, pv - h1);
    }
}

// ---------------- bn2 + output head ----------------
__global__ __launch_bounds__(256) void head_kernel(
    const float* __restrict__ latent,
    const float* __restrict__ bn2_g, const float* __restrict__ bn2_b,
    const float* __restrict__ bn2_rm, const float* __restrict__ bn2_rv,
    const float* __restrict__ out_w, const float* __restrict__ out_b,
    float* __restrict__ out)
{
    __shared__ float lw[OUT * LAT];
    __shared__ float ls[16][LAT];
    __shared__ float scale[LAT], shift[LAT];
    const int b0 = blockIdx.x * 16;
    const int tid = threadIdx.x;

    if (tid < LAT) {
        float s = bn2_g[tid] * rsqrtf(bn2_rv[tid] + EPS);
        scale[tid] = s;
        shift[tid] = bn2_b[tid] - bn2_rm[tid] * s;
    }
    for (int i = tid; i < OUT * LAT; i += 256) lw[i] = out_w[i];
    __syncthreads();

    for (int i = tid; i < 16 * LAT; i += 256) {
        int r = i / LAT, j = i % LAT;
        ls[r][j] = latent[(size_t)(b0 + r) * LAT + j] * scale[j] + shift[j];
    }
    __syncthreads();

    for (int idx = tid; idx < 16 * OUT; idx += 256) {
        int r = idx / OUT, o = idx % OUT;
        float acc = out_b[o];
        #pragma unroll 16
        for (int j = 0; j < LAT; j++) acc += ls[r][j] * lw[o * LAT + j];
        out[(size_t)(b0 + r) * OUT + o] = acc;
    }
}

// ---------------- host launch ----------------
extern "C" void kernel_launch(void* const* d_in, const int* in_sizes, int n_in,
                              void* d_out, int out_size)
{
    const float* x        = (const float*)d_in[0];
    const float* conv1_w  = (const float*)d_in[1];
    const float* conv1_b  = (const float*)d_in[2];
    const float* bn1_g    = (const float*)d_in[3];
    const float* bn1_b    = (const float*)d_in[4];
    const float* bn1_rm   = (const float*)d_in[5];
    const float* bn1_rv   = (const float*)d_in[6];
    const float* comp_w   = (const float*)d_in[7];
    const float* comp_b   = (const float*)d_in[8];
    const float* proj_w   = (const float*)d_in[9];
    const float* proj_b   = (const float*)d_in[10];
    const float* gates_w  = (const float*)d_in[11];
    const float* gates_b  = (const float*)d_in[12];
    const float* retention= (const float*)d_in[13];
    const float* expln_g  = (const float*)d_in[14];
    const float* expln_b  = (const float*)d_in[15];
    const float* ln_g     = (const float*)d_in[16];
    const float* ln_b     = (const float*)d_in[17];
    const float* attn_in_w= (const float*)d_in[18];
    const float* attn_in_b= (const float*)d_in[19];
    const float* attn_out_w=(const float*)d_in[20];
    const float* attn_out_b=(const float*)d_in[21];
    const float* bneck_w  = (const float*)d_in[22];
    const float* bneck_b  = (const float*)d_in[23];
    const float* bn2_g    = (const float*)d_in[24];
    const float* bn2_b    = (const float*)d_in[25];
    const float* bn2_rm   = (const float*)d_in[26];
    const float* bn2_rv   = (const float*)d_in[27];
    const float* out_w    = (const float*)d_in[28];
    const float* out_b    = (const float*)d_in[29];
    float* out = (float*)d_out;

    // one-time stream/event resources (host-side only; no device allocation)
    static cudaStream_t s1 = nullptr, s2 = nullptr;
    static cudaEvent_t ev0[TS], evg1[TS], evs1[TS], evfork, evw, evend, evkv;
    if (!s1) {
        int loPrio = 0, hiPrio = 0;
        cudaDeviceGetStreamPriorityRange(&loPrio, &hiPrio);
        cudaStreamCreateWithPriority(&s1, cudaStreamNonBlocking, loPrio);
        cudaStreamCreateWithPriority(&s2, cudaStreamNonBlocking, loPrio);
        for (int i = 0; i < TS; i++) {
            cudaEventCreateWithFlags(&ev0[i], cudaEventDisableTiming);
            cudaEventCreateWithFlags(&evg1[i], cudaEventDisableTiming);
            cudaEventCreateWithFlags(&evs1[i], cudaEventDisableTiming);
        }
        cudaEventCreateWithFlags(&evfork, cudaEventDisableTiming);
        cudaEventCreateWithFlags(&evw, cudaEventDisableTiming);
        cudaEventCreateWithFlags(&evend, cudaEventDisableTiming);
        cudaEventCreateWithFlags(&evkv, cudaEventDisableTiming);
        cudaFuncSetAttribute(gemm_bf16, cudaFuncAttributeMaxDynamicSharedMemorySize,
                             GEMM_SMEM_BYTES);
    }

    float *G0, *G1, *c, *kv, *q, *lat;
    uint32_t *combH, *combL, *seqH, *seqL, *hH, *hL, *attH, *attL, *finH, *finL, *Wh, *Wl;
    cudaGetSymbolAddress((void**)&G0,       d_G0);
    cudaGetSymbolAddress((void**)&G1,       d_G1);
    cudaGetSymbolAddress((void**)&c,        d_c);
    cudaGetSymbolAddress((void**)&kv,       d_kv);
    cudaGetSymbolAddress((void**)&q,        d_q);
    cudaGetSymbolAddress((void**)&lat,      d_lat);
    cudaGetSymbolAddress((void**)&combH,    d_combH);
    cudaGetSymbolAddress((void**)&combL,    d_combL);
    cudaGetSymbolAddress((void**)&seqH,     d_seqH);
    cudaGetSymbolAddress((void**)&seqL,     d_seqL);
    cudaGetSymbolAddress((void**)&hH,       d_hH);
    cudaGetSymbolAddress((void**)&hL,       d_hL);
    cudaGetSymbolAddress((void**)&attH,     d_attH);
    cudaGetSymbolAddress((void**)&attL,     d_attL);
    cudaGetSymbolAddress((void**)&finH,     d_finH);
    cudaGetSymbolAddress((void**)&finL,     d_finL);
    cudaGetSymbolAddress((void**)&Wh,       d_Wh);
    cudaGetSymbolAddress((void**)&Wl,       d_Wl);

    uint32_t* h0H_[2] = { hH, hH + (size_t)B * HW };
    uint32_t* h0L_[2] = { hL, hL + (size_t)B * HW };
    uint32_t* h1H = hH + (size_t)2 * B * HW;
    uint32_t* h1L = hL + (size_t)2 * B * HW;
    float* c0 = c;
    float* c1 = c + (size_t)B * H;

    // legal capture fork: record on origin stream FIRST, then s1 joins via wait
    cudaEventRecord(evfork, 0);
    cudaStreamWaitEvent(s1, evfork, 0);
    split4_kernel<<<4096, 256, 0, s1>>>(
        gates_w,    Wh + OFF_W0,   Wl + OFF_W0,   NG * K2H,
        attn_in_w,  Wh + OFF_AIN,  Wl + OFF_AIN,  3 * H * H / 2,
        attn_out_w, Wh + OFF_AOUT, Wl + OFF_AOUT, H * H / 2,
        bneck_w,    Wh + OFF_BNK,  Wl + OFF_BNK,  LAT * H / 2);
    cudaEventRecord(evw, s1);

    zero3_kernel<<<2048, 512>>>(c, 2 * B * H,
                                (float*)hH, 3 * B * HW,
                                (float*)hL, 3 * B * HW);
    frontend_kernel<<<B, 256>>>(x, conv1_w, conv1_b, bn1_g, bn1_b, bn1_rm, bn1_rv,
                                comp_w, comp_b, proj_w, proj_b, combH, combL);

    const float* gb0 = gates_b;
    const float* gb1 = gates_b + NG;
    dim3 gemm_grid(B / 128, NG / 128);   // 640 CTAs

    // prologue: G0(0) = [comb(0) | h0(zero)] @ W0 + gb0  (needs weights)
    cudaStreamWaitEvent(0, evw, 0);
    gemm_bf16<<<gemm_grid, 256, GEMM_SMEM_BYTES>>>(
        combH, combL, TS * HW, HW, h0H_[1], h0L_[1], HW,
        Wh + OFF_W0, Wl + OFF_W0, 2 * HW, gb0, G0, NG, nullptr, nullptr, NG);
    gate_kernel<<<B / 8, 256>>>(G0, h0H_[0], h0L_[0], c0,
                                retention, expln_g, expln_b, ln_g, ln_b,
                                nullptr, nullptr);
    cudaEventRecord(ev0[0], 0);

    // two-chain scan + interleaved kv chunks
    for (int t = 0; t < TS; t++) {
        const int p = t & 1;
        // chain 1 (s1): G1(t) = [h0(t) | h1(t-1)] @ W1 ; gate1(t) -> h1, seq(t)
        cudaStreamWaitEvent(s1, ev0[t], 0);
        gemm_bf16<<<gemm_grid, 256, GEMM_SMEM_BYTES, s1>>>(
            h0H_[p], h0L_[p], HW, HW, h1H, h1L, HW,
            Wh + OFF_W1, Wl + OFF_W1, 2 * HW, gb1, G1, NG, nullptr, nullptr, NG);
        cudaEventRecord(evg1[t], s1);
        gate_kernel<<<B / 8, 256, 0, s1>>>(
            G1, h1H, h1L, c1,
            retention + H, expln_g + H, expln_b + H, ln_g + H, ln_b + H,
            seqH + (size_t)t * HW, seqL + (size_t)t * HW);
        cudaEventRecord(evs1[t], s1);

        // kv chunk for timestep t (s2): seq(t) @ W_kv -> kv rows (b*TS+t)
        cudaStreamWaitEvent(s2, evs1[t], 0);
        gemm_bf16<<<dim3(B / 128, K2H / 128), 256, GEMM_SMEM_BYTES, s2>>>(
            seqH + (size_t)t * HW, seqL + (size_t)t * HW, TS * HW, HW,
            seqH, seqL, HW,
            Wh + OFF_AIN + (size_t)H * H / 2, Wl + OFF_AIN + (size_t)H * H / 2, HW,
            attn_in_b + H, kv + (size_t)t * K2H, TS * K2H, nullptr, nullptr, K2H);

        // chain 0 (default): G0(t+1) ; gate0(t+1) -> h0[p^1]
        if (t + 1 < TS) {
            gemm_bf16<<<gemm_grid, 256, GEMM_SMEM_BYTES>>>(
                combH + (size_t)(t + 1) * HW, combL + (size_t)(t + 1) * HW, TS * HW, HW,
                h0H_[p], h0L_[p], HW,
                Wh + OFF_W0, Wl + OFF_W0, 2 * HW, gb0, G0, NG, nullptr, nullptr, NG);
            if (t >= 1) cudaStreamWaitEvent(0, evg1[t - 1], 0);   // h0[p^1] WAR guard
            gate_kernel<<<B / 8, 256>>>(G0, h0H_[p ^ 1], h0L_[p ^ 1], c0,
                                        retention, expln_g, expln_b, ln_g, ln_b,
                                        nullptr, nullptr);
            cudaEventRecord(ev0[t + 1], 0);
        }
    }

    // q projection on s1 (ordered after gate1(TS-1)); overlaps last kv chunks
    gemm_bf16<<<dim3(B / 128, H / 128), 256, GEMM_SMEM_BYTES, s1>>>(
        seqH + (size_t)(TS - 1) * HW, seqL + (size_t)(TS - 1) * HW, TS * HW, HW,
        seqH, seqL, HW,
        Wh + OFF_AIN, Wl + OFF_AIN, HW, attn_in_b, q, H, nullptr, nullptr, H);
    cudaEventRecord(evend, s1);
    cudaEventRecord(evkv, s2);
    cudaStreamWaitEvent(0, evend, 0);
    cudaStreamWaitEvent(0, evkv, 0);

    attn_kernel<<<dim3(B, NH), 128>>>(q, kv, attH, attL);
    gemm_bf16<<<dim3(B / 128, H / 128), 256, GEMM_SMEM_BYTES>>>(
        attH, attL, HW, HW, attH, attL, HW,
        Wh + OFF_AOUT, Wl + OFF_AOUT, HW, attn_out_b, nullptr, H, finH, finL, H);
    gemm_bf16<<<dim3(B / 128, LAT / 128), 256, GEMM_SMEM_BYTES>>>(
        finH, finL, HW, HW, finH, finL, HW,
        Wh + OFF_BNK, Wl + OFF_BNK, HW, bneck_b, lat, LAT, nullptr, nullptr, LAT);
    head_kernel<<<B / 16, 256>>>(lat, bn2_g, bn2_b, bn2_rm, bn2_rv, out_w, out_b, out);
}